// round 14
// baseline (speedup 1.0000x reference)
#include <cuda_runtime.h>
#include <cuda_fp16.h>
#include <cstdint>
#include <math.h>

#define B_ 128
#define S_ 4096
#define D_ 256
#define U_ 128

#define NSPLIT 8
#define GRID_SC 148
#define NUNIT (B_ * NSPLIT)

// ---------------- device scratch ----------------
__device__ float g_qpb[B_ * U_];
__device__ float g_score[B_ * S_];        // stores e = exp(score - M)
__device__ float g_ctxp[NSPLIT * B_ * D_];
__device__ float g_zp[NSPLIT * B_];
__device__ float g_invZ[B_];

// ---------------- helpers ----------------
__device__ __forceinline__ uint32_t smem_u32(const void* p) {
    uint32_t a;
    asm("{ .reg .u64 t; cvta.to.shared.u64 t, %1; cvt.u32.u64 %0, t; }" : "=r"(a) : "l"(p));
    return a;
}

#define LDSM4(r, addr) \
    asm volatile("ldmatrix.sync.aligned.m8n8.x4.shared.b16 {%0,%1,%2,%3}, [%4];" \
        : "=r"((r)[0]), "=r"((r)[1]), "=r"((r)[2]), "=r"((r)[3]) : "r"(addr))

// m16n8k16 fp16 MMA, fp32 accum
__device__ __forceinline__ void mma_f16(float* d, const uint32_t* a,
                                        uint32_t b0, uint32_t b1) {
    asm volatile(
        "mma.sync.aligned.m16n8k16.row.col.f32.f16.f16.f32 "
        "{%0,%1,%2,%3}, {%4,%5,%6,%7}, {%8,%9}, {%0,%1,%2,%3};"
        : "+f"(d[0]), "+f"(d[1]), "+f"(d[2]), "+f"(d[3])
        : "r"(a[0]), "r"(a[1]), "r"(a[2]), "r"(a[3]), "r"(b0), "r"(b1));
}

__device__ __forceinline__ float tanh_approx(float x) {
    float y;
    asm("tanh.approx.f32 %0, %1;" : "=f"(y) : "f"(x));
    return y;
}

// ---------------------------------------------------------------------------
// K1: qpb[b,u] = query[b,:]@W1[:,u] + b1[u] + b2[u]
// ---------------------------------------------------------------------------
__global__ void qproj_kernel(const float* __restrict__ query,
                             const float* __restrict__ W1,
                             const float* __restrict__ b1,
                             const float* __restrict__ b2) {
    int b = blockIdx.x;
    int u = threadIdx.x;
    __shared__ float sq[D_];
    for (int i = threadIdx.x; i < D_; i += blockDim.x) sq[i] = query[b * D_ + i];
    __syncthreads();
    float acc = b1[u] + b2[u];
    #pragma unroll 8
    for (int d = 0; d < D_; d++) acc += sq[d] * W1[d * U_ + u];
    g_qpb[b * U_ + u] = acc;
}

// ---------------------------------------------------------------------------
// K2: PERSISTENT fused score + context, fp16 mma, fixed-shift softmax,
//     DEFERRED context (tile 0's e*v accumulation overlapped with tile 1 MMA).
// ---------------------------------------------------------------------------
#define AH_STR   80
#define AH_BUF_B (256 * AH_STR)        // 20480 B / buffer
#define BH_STR   528                   // 264 halfs

#define OFF_E_F   1280                 // sE: 2 x 256 floats
#define OFF_W_F   1792                 // swB: 16 floats (pad to 32)
#define OFF_AH_F  1824
#define OFF_BH_F  (OFF_AH_F + (2 * AH_BUF_B) / 4)   // 12064
#define SMEM_F    (OFF_BH_F + (U_ * BH_STR) / 4)    // 28960 floats
#define SMEM_SC   (SMEM_F * 4)                      // 115840 bytes

#define NTILE   2
#define KCHUNKS 8
#define NCHUNK  (NTILE * KCHUNKS)   // 16

__global__ __launch_bounds__(512, 1)
void score_mma_kernel(const float* __restrict__ values,
                      const float* __restrict__ W2,
                      const float* __restrict__ Wv,
                      const float* __restrict__ bv) {
    extern __shared__ float sm[];
    float* sQ   = sm;
    float* sWv  = sm + 128;
    float* sred = sm + 256;
    float* sE   = sm + OFF_E_F;       // [2][256]
    float* swB  = sm + OFF_W_F;
    char*  sAh  = (char*)sm + OFF_AH_F * 4;
    __half* sBTh = (__half*)(sm + OFF_BH_F);

    const int tid  = threadIdx.x;
    const int lane = tid & 31;
    const int wid  = tid >> 5;
    const int g    = lane >> 2;
    const int q    = lane & 3;
    const int wm   = wid >> 2;
    const int wn   = wid & 3;
    const float bvv = bv[0];

    const uint32_t smAh_b = smem_u32(sAh);
    const uint32_t smBh_b = smem_u32(sBTh);

    // ---- one-time: B = W2^T fp16 [u][k], Wv ----
    for (int idx = tid; idx < D_ * U_; idx += 512) {
        int k = idx >> 7, u = idx & 127;
        sBTh[u * 264 + k] = __float2half_rn(W2[idx]);
    }
    for (int i = tid; i < U_; i += 512) sWv[i] = Wv[i];
    __syncthreads();

    // fixed softmax shift: M = bv + sum|Wv| (exact upper bound; tanh <= 1)
    float Mfix = bvv;
    #pragma unroll 8
    for (int i = 0; i < U_; i++) Mfix += fabsf(sWv[i]);

    // ---- ldmatrix per-thread offsets ----
    const int a_r  = (lane & 7) + (((lane >> 3) & 1) * 8);
    const int a_kb = (lane >= 16) ? 16 : 0;
    uint32_t aoff[4];
    #pragma unroll
    for (int i = 0; i < 4; i++)
        aoff[i] = (uint32_t)((wm * 64 + i * 16 + a_r) * AH_STR + a_kb);
    const int b_r  = (lane & 7) + ((lane >= 16) ? 8 : 0);
    const int b_kb = ((lane >> 3) & 1) * 16;
    uint32_t boff[2];
    #pragma unroll
    for (int jt = 0; jt < 2; jt++)
        boff[jt] = smBh_b + (uint32_t)((wn * 32 + jt * 16 + b_r) * BH_STR + b_kb);

    const int dq = tid & 63;
    const int sh = tid >> 6;

    int crow[4], cf4[4];
    #pragma unroll
    for (int it = 0; it < 4; it++) {
        int idx = tid + it * 512;
        crow[it] = idx >> 3;
        cf4[it]  = idx & 7;
    }

    // ================= persistent unit loop =================
    for (int unit = blockIdx.x; unit < NUNIT; unit += GRID_SC) {
        const int b  = unit >> 3;
        const int ss = unit & 7;
        const int s0 = ss * 512;

        float4 va[4];
        auto ldg_chunk = [&](int gc) {
            int mm = gc >> 3, kc = gc & 7;
            const float* src = values + ((size_t)(b * S_ + s0 + mm * 256)) * D_ + kc * 32;
            #pragma unroll
            for (int it = 0; it < 4; it++)
                va[it] = *reinterpret_cast<const float4*>(
                    src + (size_t)crow[it] * D_ + cf4[it] * 4);
        };
        auto cvt_sts = [&](int gc) {
            char* abuf = sAh + (gc & 1) * AH_BUF_B;
            #pragma unroll
            for (int it = 0; it < 4; it++) {
                __half2 h0 = __floats2half2_rn(va[it].x, va[it].y);
                __half2 h1 = __floats2half2_rn(va[it].z, va[it].w);
                uint2 pk;
                pk.x = *reinterpret_cast<uint32_t*>(&h0);
                pk.y = *reinterpret_cast<uint32_t*>(&h1);
                *reinterpret_cast<uint2*>(abuf + crow[it] * AH_STR + cf4[it] * 8) = pk;
            }
        };

        // per-unit context source pointers (tile 0 / tile 1)
        const float4* vsrc0 = (const float4*)(values +
            ((size_t)(b * S_ + s0 + sh * 32)) * D_) + dq;
        const float4* vsrc1 = (const float4*)(values +
            ((size_t)(b * S_ + s0 + 256 + sh * 32)) * D_) + dq;
        const float* eb0 = sE + sh * 32;          // tile 0 buffer
        const float* eb1 = sE + 256 + sh * 32;    // tile 1 buffer

        // prologue: chunk 0 into buf0
        ldg_chunk(0);
        for (int i = tid; i < U_; i += 512) sQ[i] = g_qpb[b * U_ + i];
        cvt_sts(0);
        __syncthreads();

        float z_run = 0.0f;
        float4 c4 = make_float4(0.f, 0.f, 0.f, 0.f);

        float acc[4][4][4];

        for (int gc = 0; gc < NCHUNK; gc++) {
            if ((gc & 7) == 0) {
                #pragma unroll
                for (int i = 0; i < 4; i++)
                    #pragma unroll
                    for (int j = 0; j < 4; j++)
                        #pragma unroll
                        for (int e = 0; e < 4; e++) acc[i][j][e] = 0.0f;
            }

            if (gc + 1 < NCHUNK) ldg_chunk(gc + 1);   // hide LDG under MMA

            // ---- MMA on chunk gc ----
            {
                uint32_t aB = smAh_b + (gc & 1) * AH_BUF_B;
                uint32_t bK = (uint32_t)((gc & 7) * 64);
                #pragma unroll
                for (int k16 = 0; k16 < 2; k16++) {
                    uint32_t a[4][4];
                    #pragma unroll
                    for (int i = 0; i < 4; i++)
                        LDSM4(a[i], aB + aoff[i] + k16 * 32);
                    uint32_t bf[2][4];
                    LDSM4(bf[0], boff[0] + bK + k16 * 32);
                    LDSM4(bf[1], boff[1] + bK + k16 * 32);
                    #pragma unroll
                    for (int j = 0; j < 4; j++) {
                        uint32_t b0 = bf[j >> 1][(j & 1) * 2];
                        uint32_t b1 = bf[j >> 1][(j & 1) * 2 + 1];
                        #pragma unroll
                        for (int i = 0; i < 4; i++)
                            mma_f16(acc[i][j], a[i], b0, b1);
                    }
                }
            }

            if (gc + 1 < NCHUNK) cvt_sts(gc + 1);

            // ---- deferred tile-0 context: 4 steps per tile-1 chunk ----
            if (gc >= 8) {
                int st = (gc & 7) * 4;
                #pragma unroll
                for (int s2 = 0; s2 < 4; s2++) {
                    float ev = eb0[st + s2];
                    float4 v = vsrc0[(size_t)(st + s2) * 64];
                    c4.x += ev * v.x; c4.y += ev * v.y;
                    c4.z += ev * v.z; c4.w += ev * v.w;
                }
            }

            if ((gc & 7) != 7) {
                __syncthreads();
                continue;
            }

            // ======== tile epilogue (gc&7==7), mt = gc>>3 ========
            const int mt = gc >> 3;
            float p[8];
            #pragma unroll
            for (int e = 0; e < 8; e++) p[e] = 0.0f;
            #pragma unroll
            for (int i = 0; i < 4; i++)
                #pragma unroll
                for (int j = 0; j < 4; j++) {
                    int ub = wn * 32 + j * 8 + q * 2;
                    float w0 = sWv[ub], w1 = sWv[ub + 1];
                    float q0 = sQ[ub],  q1 = sQ[ub + 1];
                    p[i * 2]     += tanh_approx(acc[i][j][0] + q0) * w0
                                  + tanh_approx(acc[i][j][1] + q1) * w1;
                    p[i * 2 + 1] += tanh_approx(acc[i][j][2] + q0) * w0
                                  + tanh_approx(acc[i][j][3] + q1) * w1;
                }
            #pragma unroll
            for (int e = 0; e < 8; e++) {
                p[e] += __shfl_xor_sync(0xffffffffu, p[e], 1);
                p[e] += __shfl_xor_sync(0xffffffffu, p[e], 2);
            }
            // sred write immediately (last sred reads were >=2 barriers ago)
            if (q == 0) {
                float* sr = sred + wn * 256 + wm * 64;
                #pragma unroll
                for (int i = 0; i < 4; i++) {
                    sr[i * 16 + g]     = p[i * 2];
                    sr[i * 16 + g + 8] = p[i * 2 + 1];
                }
            }
            __syncthreads();   // sred visible; also chunk barrier for STS(gc+1)

            float e = 0.0f;
            if (tid < 256) {
                float myscore = sred[tid] + sred[256 + tid] + sred[512 + tid]
                              + sred[768 + tid] + bvv;
                e = __expf(myscore - Mfix);
                g_score[(size_t)b * S_ + s0 + mt * 256 + tid] = e;
                sE[(mt & 1) * 256 + tid] = e;
            }
            float ls = e;
            #pragma unroll
            for (int off = 16; off > 0; off >>= 1)
                ls += __shfl_xor_sync(0xffffffffu, ls, off);
            if (lane == 0) swB[wid] = ls;
            __syncthreads();   // swB + sE visible
            float z_tile = 0.0f;
            #pragma unroll
            for (int i = 0; i < 16; i++) z_tile += swB[i];
            z_run += z_tile;
        }

        // ---- tile-1 context (non-overlapped tail) ----
        #pragma unroll 4
        for (int s = 0; s < 32; s++) {
            float ev = eb1[s];
            float4 v = vsrc1[(size_t)s * 64];
            c4.x += ev * v.x; c4.y += ev * v.y;
            c4.z += ev * v.z; c4.w += ev * v.w;
        }

        // ---- combine 8 stripes via sred ----
        __syncthreads();
        if (sh < 4) ((float4*)sred)[sh * 64 + dq] = c4;
        __syncthreads();
        float v = 0.0f;
        if (tid < 256) {
            #pragma unroll
            for (int i = 0; i < 4; i++) v += sred[i * 256 + tid];
        }
        __syncthreads();
        if (sh >= 4) ((float4*)sred)[(sh - 4) * 64 + dq] = c4;
        __syncthreads();
        if (tid < 256) {
            #pragma unroll
            for (int i = 0; i < 4; i++) v += sred[i * 256 + tid];
            g_ctxp[(size_t)ss * B_ * D_ + b * D_ + tid] = v;
        }
        if (tid == 0) g_zp[ss * B_ + b] = z_run;
        __syncthreads();
    }
}

// ---------------------------------------------------------------------------
// K3: combine partials -> context; Z = sum z_i.
// ---------------------------------------------------------------------------
__global__ void ctx_reduce_kernel(float* __restrict__ ctx) {
    int b = blockIdx.x;
    int d = threadIdx.x;  // 256
    float Z = 0.0f;
    #pragma unroll
    for (int i = 0; i < NSPLIT; i++) Z += g_zp[i * B_ + b];
    float invZ = 1.0f / Z;
    if (d == 0) g_invZ[b] = invZ;
    float a = 0.0f;
    #pragma unroll
    for (int i = 0; i < NSPLIT; i++)
        a += g_ctxp[(size_t)i * B_ * D_ + b * D_ + d];
    ctx[b * D_ + d] = a * invZ;
}

// ---------------------------------------------------------------------------
// K4: weights = e * invZ
// ---------------------------------------------------------------------------
__global__ __launch_bounds__(256)
void weights_kernel(float* __restrict__ out_w) {
    int idx = blockIdx.x * 256 + threadIdx.x;
    int b = idx >> 12;
    out_w[idx] = g_score[idx] * g_invZ[b];
}

// ---------------------------------------------------------------------------
extern "C" void kernel_launch(void* const* d_in, const int* in_sizes, int n_in,
                              void* d_out, int out_size) {
    const float* query  = (const float*)d_in[0];
    const float* values = (const float*)d_in[1];
    const float* W1     = (const float*)d_in[2];
    const float* b1     = (const float*)d_in[3];
    const float* W2     = (const float*)d_in[4];
    const float* b2     = (const float*)d_in[5];
    const float* Wv     = (const float*)d_in[6];
    const float* bv     = (const float*)d_in[7];

    float* out  = (float*)d_out;
    float* ctx  = out;
    float* wout = out + B_ * D_;

    cudaFuncSetAttribute(score_mma_kernel,
                         cudaFuncAttributeMaxDynamicSharedMemorySize, SMEM_SC);

    qproj_kernel<<<B_, U_>>>(query, W1, b1, b2);
    score_mma_kernel<<<GRID_SC, 512, SMEM_SC>>>(values, W2, Wv, bv);
    ctx_reduce_kernel<<<B_, 256>>>(ctx);
    weights_kernel<<<(B_ * S_) / 256, 256>>>(wout);
}

// round 15
// speedup vs baseline: 1.1571x; 1.1571x over previous
#include <cuda_runtime.h>
#include <cuda_fp16.h>
#include <cstdint>
#include <math.h>

#define B_ 128
#define S_ 4096
#define D_ 256
#define U_ 128

#define NSPLIT 8
#define GRID_SC 148
#define NUNIT (B_ * NSPLIT)

// ---------------- device scratch ----------------
__device__ float g_qpb[B_ * U_];
__device__ float g_score[B_ * S_];        // stores e = exp(score - M)
__device__ float g_ctxp[NSPLIT * B_ * D_];
__device__ float g_zp[NSPLIT * B_];
__device__ float g_invZ[B_];

// ---------------- helpers ----------------
__device__ __forceinline__ uint32_t smem_u32(const void* p) {
    uint32_t a;
    asm("{ .reg .u64 t; cvta.to.shared.u64 t, %1; cvt.u32.u64 %0, t; }" : "=r"(a) : "l"(p));
    return a;
}

#define LDSM4(r, addr) \
    asm volatile("ldmatrix.sync.aligned.m8n8.x4.shared.b16 {%0,%1,%2,%3}, [%4];" \
        : "=r"((r)[0]), "=r"((r)[1]), "=r"((r)[2]), "=r"((r)[3]) : "r"(addr))

__device__ __forceinline__ void mma_f16(float* d, const uint32_t* a,
                                        uint32_t b0, uint32_t b1) {
    asm volatile(
        "mma.sync.aligned.m16n8k16.row.col.f32.f16.f16.f32 "
        "{%0,%1,%2,%3}, {%4,%5,%6,%7}, {%8,%9}, {%0,%1,%2,%3};"
        : "+f"(d[0]), "+f"(d[1]), "+f"(d[2]), "+f"(d[3])
        : "r"(a[0]), "r"(a[1]), "r"(a[2]), "r"(a[3]), "r"(b0), "r"(b1));
}

__device__ __forceinline__ float tanh_approx(float x) {
    float y;
    asm("tanh.approx.f32 %0, %1;" : "=f"(y) : "f"(x));
    return y;
}

// ---------------------------------------------------------------------------
// K1: qpb[b,u] = query[b,:]@W1[:,u] + b1[u] + b2[u]
// ---------------------------------------------------------------------------
__global__ void qproj_kernel(const float* __restrict__ query,
                             const float* __restrict__ W1,
                             const float* __restrict__ b1,
                             const float* __restrict__ b2) {
    int b = blockIdx.x;
    int u = threadIdx.x;
    __shared__ float sq[D_];
    for (int i = threadIdx.x; i < D_; i += blockDim.x) sq[i] = query[b * D_ + i];
    __syncthreads();
    float acc = b1[u] + b2[u];
    #pragma unroll 8
    for (int d = 0; d < D_; d++) acc += sq[d] * W1[d * U_ + u];
    g_qpb[b * U_ + u] = acc;
}

// ---------------------------------------------------------------------------
// K2: PERSISTENT fused score + context. fp16 m16n8k16 mma.
//   Tiles of 128 seq with FULL K=256 resident in fp16 smem (double-buffered).
//   Context accumulation reads fp16 from smem -> values read from DRAM ONCE.
//   148 CTAs x 512 thr (16 warps, 4Mx4N, warp tile 32x32).
//   Unit = 512 seq = 4 tiles. Next tile (or next unit's tile 0) is loaded
//   (LDG->cvt->STS) interleaved at 4 phase points inside the MMA k16 sweep.
// ---------------------------------------------------------------------------
#define TROW_B   528                    // fp16 row stride bytes (264 halfs)
#define ABUF_B   (128 * TROW_B)         // 67584 B per tile buffer

#define OFF_SRED 256                    // 1024 floats
#define OFF_E_F  1280                   // 128 floats
#define OFF_WB_F 1408                   // 16 floats (pad to 1424)
#define OFF_AH_F 1424
#define OFF_BH_F (OFF_AH_F + (2 * ABUF_B) / 4)    // 35216
#define SMEM_F   (OFF_BH_F + (U_ * TROW_B) / 4)   // 52112 floats
#define SMEM_SC  (SMEM_F * 4)                     // 208448 bytes

__global__ __launch_bounds__(512, 1)
void score_mma_kernel(const float* __restrict__ values,
                      const float* __restrict__ W2,
                      const float* __restrict__ Wv,
                      const float* __restrict__ bv) {
    extern __shared__ float sm[];
    float* sQ   = sm;
    float* sWv  = sm + 128;
    float* sred = sm + OFF_SRED;
    float* sE   = sm + OFF_E_F;
    float* swB  = sm + OFF_WB_F;
    char*  sAh  = (char*)sm + OFF_AH_F * 4;
    __half* sBTh = (__half*)(sm + OFF_BH_F);

    const int tid  = threadIdx.x;
    const int lane = tid & 31;
    const int wid  = tid >> 5;
    const int g    = lane >> 2;
    const int q    = lane & 3;
    const int wm   = wid >> 2;      // warp M (0..3): 32 seq rows
    const int wn   = wid & 3;       // warp N (0..3): 32 units
    const float bvv = bv[0];

    const uint32_t smAh_b = smem_u32(sAh);
    const uint32_t smBh_b = smem_u32(sBTh);

    // ---- one-time: B = W2^T fp16 [u][k], Wv ----
    for (int idx = tid; idx < D_ * U_; idx += 512) {
        int k = idx >> 7, u = idx & 127;
        sBTh[u * 264 + k] = __float2half_rn(W2[idx]);
    }
    for (int i = tid; i < U_; i += 512) sWv[i] = Wv[i];
    __syncthreads();

    // fixed softmax shift: M = bv + sum|Wv| (exact upper bound; tanh <= 1)
    float Mfix = bvv;
    #pragma unroll 8
    for (int i = 0; i < U_; i++) Mfix += fabsf(sWv[i]);

    // ---- ldmatrix per-thread offsets (m16k16 frags) ----
    const int a_r  = (lane & 7) + (((lane >> 3) & 1) * 8);
    const int a_kb = (lane >= 16) ? 16 : 0;
    uint32_t aoff[2];
    #pragma unroll
    for (int i = 0; i < 2; i++)
        aoff[i] = (uint32_t)((wm * 32 + i * 16 + a_r) * TROW_B + a_kb);
    const int b_r  = (lane & 7) + ((lane >= 16) ? 8 : 0);
    const int b_kb = ((lane >> 3) & 1) * 16;
    uint32_t boff[2];
    #pragma unroll
    for (int jt = 0; jt < 2; jt++)
        boff[jt] = smBh_b + (uint32_t)((wn * 32 + jt * 16 + b_r) * TROW_B + b_kb);

    const int dq = tid & 63;   // d-group (4 floats)
    const int sh = tid >> 6;   // seq stripe (16 rows of the 128-row tile)

    float4 va[4];
    // load phase p (4 granules) of a tile from global
    auto ldg_phase = [&](const float* vb, int p) {
        #pragma unroll
        for (int k = 0; k < 4; k++) {
            int idx = tid + (p * 4 + k) * 512;
            int row = idx >> 6, f4 = idx & 63;
            va[k] = *reinterpret_cast<const float4*>(vb + (size_t)row * D_ + f4 * 4);
        }
    };
    auto sts_phase = [&](char* abuf, int p) {
        #pragma unroll
        for (int k = 0; k < 4; k++) {
            int idx = tid + (p * 4 + k) * 512;
            int row = idx >> 6, f4 = idx & 63;
            __half2 h0 = __floats2half2_rn(va[k].x, va[k].y);
            __half2 h1 = __floats2half2_rn(va[k].z, va[k].w);
            uint2 pk;
            pk.x = *reinterpret_cast<uint32_t*>(&h0);
            pk.y = *reinterpret_cast<uint32_t*>(&h1);
            *reinterpret_cast<uint2*>(abuf + row * TROW_B + f4 * 8) = pk;
        }
    };

    bool first = true;

    // ================= persistent unit loop =================
    for (int unit = blockIdx.x; unit < NUNIT; unit += GRID_SC) {
        const int b  = unit >> 3;
        const int ss = unit & 7;
        const int s0 = ss * 512;
        const float* vb = values + (size_t)(b * S_ + s0) * D_;

        const bool hnu = (unit + GRID_SC) < NUNIT;
        const int  bn  = (unit + GRID_SC) >> 3;
        const int  ssn = (unit + GRID_SC) & 7;

        if (first) {
            // prologue (once per CTA): tile 0 into buf0 + sQ
            #pragma unroll
            for (int p = 0; p < 4; p++) { ldg_phase(vb, p); sts_phase(sAh, p); }
            if (tid < 128) sQ[tid] = g_qpb[b * U_ + tid];
            first = false;
            __syncthreads();
        }

        float z_run = 0.0f;
        float4 c4 = make_float4(0.f, 0.f, 0.f, 0.f);
        float qv = 0.0f;

        for (int t = 0; t < 4; t++) {
            // next-load target
            bool hn;
            const float* vbn = vb;
            char* nbuf = sAh;
            if (t < 3) {
                hn = true;
                vbn = vb + (size_t)((t + 1) * 128) * D_;
                nbuf = sAh + ((t + 1) & 1) * ABUF_B;
            } else {
                hn = hnu;
                if (hn) {
                    vbn = values + (size_t)(bn * S_ + ssn * 512) * D_;
                    nbuf = sAh;   // next unit tile 0 -> buf0 (t parity restarts)
                    if (tid < 128) qv = g_qpb[bn * U_ + tid];
                }
            }

            float acc[2][4][4];
            #pragma unroll
            for (int i = 0; i < 2; i++)
                #pragma unroll
                for (int j = 0; j < 4; j++)
                    #pragma unroll
                    for (int e = 0; e < 4; e++) acc[i][j][e] = 0.0f;

            // ---- MMA sweep over K=256 (16 k16 steps), next-tile load interleaved ----
            const uint32_t aB = smAh_b + (t & 1) * ABUF_B;
            #pragma unroll
            for (int k16 = 0; k16 < 16; k16++) {
                if ((k16 & 3) == 0 && hn) {
                    int p = k16 >> 2;
                    if (p > 0) sts_phase(nbuf, p - 1);
                    ldg_phase(vbn, p);
                }
                uint32_t a[2][4];
                #pragma unroll
                for (int i = 0; i < 2; i++)
                    LDSM4(a[i], aB + aoff[i] + k16 * 32);
                uint32_t bf[2][4];
                LDSM4(bf[0], boff[0] + k16 * 32);
                LDSM4(bf[1], boff[1] + k16 * 32);
                #pragma unroll
                for (int j = 0; j < 4; j++) {
                    uint32_t b0 = bf[j >> 1][(j & 1) * 2];
                    uint32_t b1 = bf[j >> 1][(j & 1) * 2 + 1];
                    #pragma unroll
                    for (int i = 0; i < 2; i++)
                        mma_f16(acc[i][j], a[i], b0, b1);
                }
            }
            if (hn) sts_phase(nbuf, 3);

            // ======== tile epilogue ========
            float p[4] = {0.f, 0.f, 0.f, 0.f};
            #pragma unroll
            for (int i = 0; i < 2; i++)
                #pragma unroll
                for (int j = 0; j < 4; j++) {
                    int ub = wn * 32 + j * 8 + q * 2;
                    float w0 = sWv[ub], w1 = sWv[ub + 1];
                    float q0 = sQ[ub],  q1 = sQ[ub + 1];
                    p[i * 2]     += tanh_approx(acc[i][j][0] + q0) * w0
                                  + tanh_approx(acc[i][j][1] + q1) * w1;
                    p[i * 2 + 1] += tanh_approx(acc[i][j][2] + q0) * w0
                                  + tanh_approx(acc[i][j][3] + q1) * w1;
                }
            #pragma unroll
            for (int e = 0; e < 4; e++) {
                p[e] += __shfl_xor_sync(0xffffffffu, p[e], 1);
                p[e] += __shfl_xor_sync(0xffffffffu, p[e], 2);
            }
            if (q == 0) {
                float* sr = sred + wn * 128 + wm * 32;
                #pragma unroll
                for (int i = 0; i < 2; i++) {
                    sr[i * 16 + g]     = p[i * 2];
                    sr[i * 16 + g + 8] = p[i * 2 + 1];
                }
            }
            __syncthreads();   // sred visible; STS of next tile drained ordering-wise

            float e = 0.0f;
            if (tid < 128) {
                float myscore = sred[tid] + sred[128 + tid] + sred[256 + tid]
                              + sred[384 + tid] + bvv;
                e = __expf(myscore - Mfix);
                g_score[(size_t)b * S_ + s0 + t * 128 + tid] = e;
                sE[tid] = e;
                float ls = e;
                #pragma unroll
                for (int off = 16; off > 0; off >>= 1)
                    ls += __shfl_xor_sync(0xffffffffu, ls, off);
                if (lane == 0) swB[wid] = ls;
            }
            __syncthreads();   // sE + swB visible; also gates next tile's LDSM
            z_run += swB[0] + swB[1] + swB[2] + swB[3];

            // ---- context from fp16 smem tile (values NOT re-read from gmem) ----
            const char* abuf = (const char*)sAh + (t & 1) * ABUF_B;
            #pragma unroll 4
            for (int s = 0; s < 16; s++) {
                int row = sh * 16 + s;
                float ev = sE[row];
                uint2 hv = *reinterpret_cast<const uint2*>(abuf + row * TROW_B + dq * 8);
                __half2 h0 = *reinterpret_cast<__half2*>(&hv.x);
                __half2 h1 = *reinterpret_cast<__half2*>(&hv.y);
                float2 f0 = __half22float2(h0);
                float2 f1 = __half22float2(h1);
                c4.x += ev * f0.x; c4.y += ev * f0.y;
                c4.z += ev * f1.x; c4.w += ev * f1.y;
            }
        }

        // ---- unit end: combine 8 stripes via sred ----
        __syncthreads();
        if (sh < 4) ((float4*)sred)[sh * 64 + dq] = c4;
        __syncthreads();
        float v = 0.0f;
        if (tid < 256) {
            #pragma unroll
            for (int i = 0; i < 4; i++) v += sred[i * 256 + tid];
        }
        __syncthreads();
        if (sh >= 4) ((float4*)sred)[(sh - 4) * 64 + dq] = c4;
        __syncthreads();
        if (tid < 256) {
            #pragma unroll
            for (int i = 0; i < 4; i++) v += sred[i * 256 + tid];
            g_ctxp[(size_t)ss * B_ * D_ + b * D_ + tid] = v;
        }
        if (tid == 0) g_zp[ss * B_ + b] = z_run;
        // stage next unit's qpb (prefetched into qv during tile 3)
        if (hnu && tid < 128) sQ[tid] = qv;
        __syncthreads();
    }
}

// ---------------------------------------------------------------------------
// K3: combine partials -> context; Z = sum z_i.
// ---------------------------------------------------------------------------
__global__ void ctx_reduce_kernel(float* __restrict__ ctx) {
    int b = blockIdx.x;
    int d = threadIdx.x;  // 256
    float Z = 0.0f;
    #pragma unroll
    for (int i = 0; i < NSPLIT; i++) Z += g_zp[i * B_ + b];
    float invZ = 1.0f / Z;
    if (d == 0) g_invZ[b] = invZ;
    float a = 0.0f;
    #pragma unroll
    for (int i = 0; i < NSPLIT; i++)
        a += g_ctxp[(size_t)i * B_ * D_ + b * D_ + d];
    ctx[b * D_ + d] = a * invZ;
}

// ---------------------------------------------------------------------------
// K4: weights = e * invZ
// ---------------------------------------------------------------------------
__global__ __launch_bounds__(256)
void weights_kernel(float* __restrict__ out_w) {
    int idx = blockIdx.x * 256 + threadIdx.x;
    int b = idx >> 12;
    out_w[idx] = g_score[idx] * g_invZ[b];
}

// ---------------------------------------------------------------------------
extern "C" void kernel_launch(void* const* d_in, const int* in_sizes, int n_in,
                              void* d_out, int out_size) {
    const float* query  = (const float*)d_in[0];
    const float* values = (const float*)d_in[1];
    const float* W1     = (const float*)d_in[2];
    const float* b1     = (const float*)d_in[3];
    const float* W2     = (const float*)d_in[4];
    const float* b2     = (const float*)d_in[5];
    const float* Wv     = (const float*)d_in[6];
    const float* bv     = (const float*)d_in[7];

    float* out  = (float*)d_out;
    float* ctx  = out;
    float* wout = out + B_ * D_;

    cudaFuncSetAttribute(score_mma_kernel,
                         cudaFuncAttributeMaxDynamicSharedMemorySize, SMEM_SC);

    qproj_kernel<<<B_, U_>>>(query, W1, b1, b2);
    score_mma_kernel<<<GRID_SC, 512, SMEM_SC>>>(values, W2, Wv, bv);
    ctx_reduce_kernel<<<B_, 256>>>(ctx);
    weights_kernel<<<(B_ * S_) / 256, 256>>>(wout);
}

// round 16
// speedup vs baseline: 1.2042x; 1.0407x over previous
#include <cuda_runtime.h>
#include <cuda_fp16.h>
#include <cstdint>
#include <math.h>

#define B_ 128
#define S_ 4096
#define D_ 256
#define U_ 128

#define NSPLIT 8
#define GRID_SC 148
#define NUNIT (B_ * NSPLIT)

// ---------------- device scratch ----------------
__device__ float g_qpb[B_ * U_];
__device__ float g_score[B_ * S_];        // stores e = exp(score - M)
__device__ float g_ctxp[NSPLIT * B_ * D_];
__device__ float g_zp[NSPLIT * B_];
__device__ float g_invZ[B_];

// ---------------- helpers ----------------
__device__ __forceinline__ uint32_t smem_u32(const void* p) {
    uint32_t a;
    asm("{ .reg .u64 t; cvta.to.shared.u64 t, %1; cvt.u32.u64 %0, t; }" : "=r"(a) : "l"(p));
    return a;
}

#define LDSM4(r, addr) \
    asm volatile("ldmatrix.sync.aligned.m8n8.x4.shared.b16 {%0,%1,%2,%3}, [%4];" \
        : "=r"((r)[0]), "=r"((r)[1]), "=r"((r)[2]), "=r"((r)[3]) : "r"(addr))

__device__ __forceinline__ void mma_f16(float* d, const uint32_t* a,
                                        uint32_t b0, uint32_t b1) {
    asm volatile(
        "mma.sync.aligned.m16n8k16.row.col.f32.f16.f16.f32 "
        "{%0,%1,%2,%3}, {%4,%5,%6,%7}, {%8,%9}, {%0,%1,%2,%3};"
        : "+f"(d[0]), "+f"(d[1]), "+f"(d[2]), "+f"(d[3])
        : "r"(a[0]), "r"(a[1]), "r"(a[2]), "r"(a[3]), "r"(b0), "r"(b1));
}

__device__ __forceinline__ float tanh_approx(float x) {
    float y;
    asm("tanh.approx.f32 %0, %1;" : "=f"(y) : "f"(x));
    return y;
}

// ---------------------------------------------------------------------------
// K1: qpb[b,u] = query[b,:]@W1[:,u] + b1[u] + b2[u]
// ---------------------------------------------------------------------------
__global__ void qproj_kernel(const float* __restrict__ query,
                             const float* __restrict__ W1,
                             const float* __restrict__ b1,
                             const float* __restrict__ b2) {
    int b = blockIdx.x;
    int u = threadIdx.x;
    __shared__ float sq[D_];
    for (int i = threadIdx.x; i < D_; i += blockDim.x) sq[i] = query[b * D_ + i];
    __syncthreads();
    float acc = b1[u] + b2[u];
    #pragma unroll 8
    for (int d = 0; d < D_; d++) acc += sq[d] * W1[d * U_ + u];
    g_qpb[b * U_ + u] = acc;
}

// ---------------------------------------------------------------------------
// K2: PERSISTENT fused score + context. fp16 m16n8k16 mma.
//   Warp grid 8(M)x2(N): warp tile 16 seq x 64 u. Score/e/z/context are
//   PAIR-local (warps 2m,2m+1, named barrier id 1+m) -> only ONE block
//   barrier per tile; pair epilogues overlap other pairs' MMA sweeps.
//   128-seq tiles, full K=256 resident fp16, double-buffered; context reads
//   fp16 from smem (values read from DRAM once).
// ---------------------------------------------------------------------------
#define TROW_B   528                    // fp16 row stride bytes (264 halfs)
#define ABUF_B   (128 * TROW_B)         // 67584 B per tile buffer

#define OFF_SRED 256                    // 2048 floats (pairbuf / c-combine)
#define OFF_ZB_F 2304                   // 16 floats
#define OFF_AH_F 2320
#define OFF_BH_F (OFF_AH_F + (2 * ABUF_B) / 4)    // 36112
#define SMEM_F   (OFF_BH_F + (U_ * TROW_B) / 4)   // 53008 floats
#define SMEM_SC  (SMEM_F * 4)                     // 212032 bytes

__global__ __launch_bounds__(512, 1)
void score_mma_kernel(const float* __restrict__ values,
                      const float* __restrict__ W2,
                      const float* __restrict__ Wv,
                      const float* __restrict__ bv) {
    extern __shared__ float sm[];
    float* sQ   = sm;
    float* sWv  = sm + 128;
    float* sred = sm + OFF_SRED;
    float* zbuf = sm + OFF_ZB_F;
    char*  sAh  = (char*)sm + OFF_AH_F * 4;
    __half* sBTh = (__half*)(sm + OFF_BH_F);

    const int tid  = threadIdx.x;
    const int lane = tid & 31;
    const int wid  = tid >> 5;
    const int g    = lane >> 2;
    const int q    = lane & 3;
    const int wm   = wid >> 1;      // pair id (0..7): 16 seq rows
    const int wn   = wid & 1;       // half (0..1): 64 units / 128 d
    const float bvv = bv[0];

    const uint32_t smAh_b = smem_u32(sAh);
    const uint32_t smBh_b = smem_u32(sBTh);

    // ---- one-time: B = W2^T fp16 [u][k], Wv ----
    for (int idx = tid; idx < D_ * U_; idx += 512) {
        int k = idx >> 7, u = idx & 127;
        sBTh[u * 264 + k] = __float2half_rn(W2[idx]);
    }
    for (int i = tid; i < U_; i += 512) sWv[i] = Wv[i];
    __syncthreads();

    // fixed softmax shift: M = bv + sum|Wv| (exact upper bound; tanh <= 1)
    float Mfix = bvv;
    #pragma unroll 8
    for (int i = 0; i < U_; i++) Mfix += fabsf(sWv[i]);

    // ---- ldmatrix per-thread offsets ----
    const int a_r  = (lane & 7) + (((lane >> 3) & 1) * 8);
    const int a_kb = (lane >= 16) ? 16 : 0;
    const uint32_t aoff = (uint32_t)((wm * 16 + a_r) * TROW_B + a_kb);
    const int b_r  = (lane & 7) + ((lane >= 16) ? 8 : 0);
    const int b_kb = ((lane >> 3) & 1) * 16;
    const uint32_t boff_base =
        smBh_b + (uint32_t)((wn * 64 + b_r) * TROW_B + b_kb);

    float4 va[4];
    auto ldg_phase = [&](const float* vb, int p) {
        #pragma unroll
        for (int k = 0; k < 4; k++) {
            int idx = tid + (p * 4 + k) * 512;
            int row = idx >> 6, f4 = idx & 63;
            va[k] = *reinterpret_cast<const float4*>(vb + (size_t)row * D_ + f4 * 4);
        }
    };
    auto sts_phase = [&](char* abuf, int p) {
        #pragma unroll
        for (int k = 0; k < 4; k++) {
            int idx = tid + (p * 4 + k) * 512;
            int row = idx >> 6, f4 = idx & 63;
            __half2 h0 = __floats2half2_rn(va[k].x, va[k].y);
            __half2 h1 = __floats2half2_rn(va[k].z, va[k].w);
            uint2 pk;
            pk.x = *reinterpret_cast<uint32_t*>(&h0);
            pk.y = *reinterpret_cast<uint32_t*>(&h1);
            *reinterpret_cast<uint2*>(abuf + row * TROW_B + f4 * 8) = pk;
        }
    };

    bool first = true;

    // ================= persistent unit loop =================
    for (int unit = blockIdx.x; unit < NUNIT; unit += GRID_SC) {
        const int b  = unit >> 3;
        const int ss = unit & 7;
        const int s0 = ss * 512;
        const float* vb = values + (size_t)(b * S_ + s0) * D_;

        const bool hnu = (unit + GRID_SC) < NUNIT;
        const int  bn  = (unit + GRID_SC) >> 3;
        const int  ssn = (unit + GRID_SC) & 7;

        if (first) {
            #pragma unroll
            for (int p = 0; p < 4; p++) { ldg_phase(vb, p); sts_phase(sAh, p); }
            if (tid < 128) sQ[tid] = g_qpb[b * U_ + tid];
            first = false;
            __syncthreads();
        }

        float z_local = 0.0f;
        float4 c4 = make_float4(0.f, 0.f, 0.f, 0.f);
        float qv = 0.0f;

        for (int t = 0; t < 4; t++) {
            bool hn;
            const float* vbn = vb;
            char* nbuf = sAh;
            if (t < 3) {
                hn = true;
                vbn = vb + (size_t)((t + 1) * 128) * D_;
                nbuf = sAh + ((t + 1) & 1) * ABUF_B;
            } else {
                hn = hnu;
                if (hn) {
                    vbn = values + (size_t)(bn * S_ + ssn * 512) * D_;
                    nbuf = sAh;
                    if (tid < 128) qv = g_qpb[bn * U_ + tid];
                }
            }

            float acc[8][4];
            #pragma unroll
            for (int j = 0; j < 8; j++)
                #pragma unroll
                for (int e = 0; e < 4; e++) acc[j][e] = 0.0f;

            // ---- MMA sweep over K=256 (16 k16), next-tile load interleaved ----
            const uint32_t aB = smAh_b + (t & 1) * ABUF_B;
            #pragma unroll
            for (int k16 = 0; k16 < 16; k16++) {
                if ((k16 & 3) == 0 && hn) {
                    int p = k16 >> 2;
                    if (p > 0) sts_phase(nbuf, p - 1);
                    ldg_phase(vbn, p);
                }
                uint32_t a[4];
                LDSM4(a, aB + aoff + k16 * 32);
                #pragma unroll
                for (int jt = 0; jt < 4; jt++) {
                    uint32_t bf[4];
                    LDSM4(bf, boff_base + (uint32_t)(jt * 16 * TROW_B) + k16 * 32);
                    mma_f16(acc[jt * 2],     a, bf[0], bf[1]);
                    mma_f16(acc[jt * 2 + 1], a, bf[2], bf[3]);
                }
            }
            if (hn) sts_phase(nbuf, 3);

            // ======== pair-local epilogue (no block barrier first) ========
            float p0 = 0.f, p1 = 0.f;
            #pragma unroll
            for (int j = 0; j < 8; j++) {
                int ub = wn * 64 + j * 8 + q * 2;
                float w0 = sWv[ub], w1 = sWv[ub + 1];
                float q0 = sQ[ub],  q1 = sQ[ub + 1];
                p0 += tanh_approx(acc[j][0] + q0) * w0
                    + tanh_approx(acc[j][1] + q1) * w1;
                p1 += tanh_approx(acc[j][2] + q0) * w0
                    + tanh_approx(acc[j][3] + q1) * w1;
            }
            p0 += __shfl_xor_sync(0xffffffffu, p0, 1);
            p0 += __shfl_xor_sync(0xffffffffu, p0, 2);
            p1 += __shfl_xor_sync(0xffffffffu, p1, 1);
            p1 += __shfl_xor_sync(0xffffffffu, p1, 2);

            float* pb = sred + wm * 32;
            if (q == 0) {
                pb[wn * 16 + g]     = p0;
                pb[wn * 16 + g + 8] = p1;
            }
            asm volatile("bar.sync %0, 64;" :: "r"(1 + wm) : "memory");
            float e0 = __expf(pb[g]      + pb[16 + g]      + bvv - Mfix);
            float e1 = __expf(pb[g + 8]  + pb[16 + g + 8]  + bvv - Mfix);
            if (wn == 0 && q == 0) {
                size_t sb = (size_t)b * S_ + s0 + t * 128 + wm * 16;
                g_score[sb + g]     = e0;
                g_score[sb + g + 8] = e1;
                z_local += e0 + e1;
            }

            // ---- context from fp16 smem (pair rows, this warp's d-half) ----
            const char* abuf = (const char*)sAh + (t & 1) * ABUF_B
                             + (wm * 16) * TROW_B + wn * 256 + lane * 8;
            #pragma unroll
            for (int r = 0; r < 16; r++) {
                float er = __shfl_sync(0xffffffffu, (r < 8) ? e0 : e1, (r & 7) << 2);
                uint2 hv = *reinterpret_cast<const uint2*>(abuf + r * TROW_B);
                __half2 h0 = *reinterpret_cast<__half2*>(&hv.x);
                __half2 h1 = *reinterpret_cast<__half2*>(&hv.y);
                float2 f0 = __half22float2(h0);
                float2 f1 = __half22float2(h1);
                c4.x += er * f0.x; c4.y += er * f0.y;
                c4.z += er * f1.x; c4.w += er * f1.y;
            }

            __syncthreads();   // single block barrier per tile
        }

        // ---- unit end: combine context + z ----
        ((float4*)sred)[wid * 32 + lane] = c4;    // 16 warps x 128 floats
        float zs = z_local;
        #pragma unroll
        for (int off = 16; off > 0; off >>= 1)
            zs += __shfl_xor_sync(0xffffffffu, zs, off);
        if (lane == 0 && wn == 0) zbuf[wm] = zs;
        __syncthreads();
        if (tid < 256) {
            float v = 0.0f;
            int wnd = tid >> 7, l4 = tid & 127;
            #pragma unroll
            for (int m8 = 0; m8 < 8; m8++)
                v += sred[(m8 * 2 + wnd) * 128 + l4];
            g_ctxp[(size_t)ss * B_ * D_ + b * D_ + tid] = v;
        }
        if (tid == 0) {
            float z = 0.0f;
            #pragma unroll
            for (int i = 0; i < 8; i++) z += zbuf[i];
            g_zp[ss * B_ + b] = z;
        }
        if (hnu && tid < 128) sQ[tid] = qv;
        __syncthreads();
    }
}

// ---------------------------------------------------------------------------
// K3: combine partials -> context; Z = sum z_i.
// ---------------------------------------------------------------------------
__global__ void ctx_reduce_kernel(float* __restrict__ ctx) {
    int b = blockIdx.x;
    int d = threadIdx.x;  // 256
    float Z = 0.0f;
    #pragma unroll
    for (int i = 0; i < NSPLIT; i++) Z += g_zp[i * B_ + b];
    float invZ = 1.0f / Z;
    if (d == 0) g_invZ[b] = invZ;
    float a = 0.0f;
    #pragma unroll
    for (int i = 0; i < NSPLIT; i++)
        a += g_ctxp[(size_t)i * B_ * D_ + b * D_ + d];
    ctx[b * D_ + d] = a * invZ;
}

// ---------------------------------------------------------------------------
// K4: weights = e * invZ
// ---------------------------------------------------------------------------
__global__ __launch_bounds__(256)
void weights_kernel(float* __restrict__ out_w) {
    int idx = blockIdx.x * 256 + threadIdx.x;
    int b = idx >> 12;
    out_w[idx] = g_score[idx] * g_invZ[b];
}

// ---------------------------------------------------------------------------
extern "C" void kernel_launch(void* const* d_in, const int* in_sizes, int n_in,
                              void* d_out, int out_size) {
    const float* query  = (const float*)d_in[0];
    const float* values = (const float*)d_in[1];
    const float* W1     = (const float*)d_in[2];
    const float* b1     = (const float*)d_in[3];
    const float* W2     = (const float*)d_in[4];
    const float* b2     = (const float*)d_in[5];
    const float* Wv     = (const float*)d_in[6];
    const float* bv     = (const float*)d_in[7];

    float* out  = (float*)d_out;
    float* ctx  = out;
    float* wout = out + B_ * D_;

    cudaFuncSetAttribute(score_mma_kernel,
                         cudaFuncAttributeMaxDynamicSharedMemorySize, SMEM_SC);

    qproj_kernel<<<B_, U_>>>(query, W1, b1, b2);
    score_mma_kernel<<<GRID_SC, 512, SMEM_SC>>>(values, W2, Wv, bv);
    ctx_reduce_kernel<<<B_, 256>>>(ctx);
    weights_kernel<<<(B_ * S_) / 256, 256>>>(wout);
}

// round 17
// speedup vs baseline: 1.2086x; 1.0037x over previous
#include <cuda_runtime.h>
#include <cuda_fp16.h>
#include <cstdint>
#include <math.h>

#define B_ 128
#define S_ 4096
#define D_ 256
#define U_ 128

#define NSPLIT 8
#define GRID_SC 148
#define NUNIT (B_ * NSPLIT)

// ---------------- device scratch ----------------
__device__ float g_qpb[B_ * U_];
__device__ float g_score[B_ * S_];        // stores e = exp(score - M)
__device__ float g_ctxp[NSPLIT * B_ * D_];
__device__ float g_zp[NSPLIT * B_];

// ---------------- helpers ----------------
__device__ __forceinline__ uint32_t smem_u32(const void* p) {
    uint32_t a;
    asm("{ .reg .u64 t; cvta.to.shared.u64 t, %1; cvt.u32.u64 %0, t; }" : "=r"(a) : "l"(p));
    return a;
}

#define LDSM4(r, addr) \
    asm volatile("ldmatrix.sync.aligned.m8n8.x4.shared.b16 {%0,%1,%2,%3}, [%4];" \
        : "=r"((r)[0]), "=r"((r)[1]), "=r"((r)[2]), "=r"((r)[3]) : "r"(addr))

__device__ __forceinline__ void mma_f16(float* d, const uint32_t* a,
                                        uint32_t b0, uint32_t b1) {
    asm volatile(
        "mma.sync.aligned.m16n8k16.row.col.f32.f16.f16.f32 "
        "{%0,%1,%2,%3}, {%4,%5,%6,%7}, {%8,%9}, {%0,%1,%2,%3};"
        : "+f"(d[0]), "+f"(d[1]), "+f"(d[2]), "+f"(d[3])
        : "r"(a[0]), "r"(a[1]), "r"(a[2]), "r"(a[3]), "r"(b0), "r"(b1));
}

__device__ __forceinline__ float tanh_approx(float x) {
    float y;
    asm("tanh.approx.f32 %0, %1;" : "=f"(y) : "f"(x));
    return y;
}

// ---------------------------------------------------------------------------
// K1: qpb[b,u] = query[b,:]@W1[:,u] + b1[u] + b2[u]
// ---------------------------------------------------------------------------
__global__ void qproj_kernel(const float* __restrict__ query,
                             const float* __restrict__ W1,
                             const float* __restrict__ b1,
                             const float* __restrict__ b2) {
    int b = blockIdx.x;
    int u = threadIdx.x;
    __shared__ float sq[D_];
    for (int i = threadIdx.x; i < D_; i += blockDim.x) sq[i] = query[b * D_ + i];
    __syncthreads();
    float acc = b1[u] + b2[u];
    #pragma unroll 8
    for (int d = 0; d < D_; d++) acc += sq[d] * W1[d * U_ + u];
    g_qpb[b * U_ + u] = acc;
}

// ---------------------------------------------------------------------------
// K2: PERSISTENT fused score + context. fp16 m16n8k16 mma.
//   Warp grid 8(M)x2(N), pair-local epilogue, 128-seq tiles with full K=256
//   resident fp16 (double-buffered); context reads fp16 from smem.
//   Load interleave phases at k16 = {2,6,10,14} (off the LDSM burst).
// ---------------------------------------------------------------------------
#define TROW_B   528                    // fp16 row stride bytes (264 halfs)
#define ABUF_B   (128 * TROW_B)         // 67584 B per tile buffer

#define OFF_SRED 256                    // 2048 floats (pairbuf / c-combine)
#define OFF_ZB_F 2304                   // 16 floats
#define OFF_AH_F 2320
#define OFF_BH_F (OFF_AH_F + (2 * ABUF_B) / 4)    // 36112
#define SMEM_F   (OFF_BH_F + (U_ * TROW_B) / 4)   // 53008 floats
#define SMEM_SC  (SMEM_F * 4)                     // 212032 bytes

__global__ __launch_bounds__(512, 1)
void score_mma_kernel(const float* __restrict__ values,
                      const float* __restrict__ W2,
                      const float* __restrict__ Wv,
                      const float* __restrict__ bv) {
    extern __shared__ float sm[];
    float* sQ   = sm;
    float* sWv  = sm + 128;
    float* sred = sm + OFF_SRED;
    float* zbuf = sm + OFF_ZB_F;
    char*  sAh  = (char*)sm + OFF_AH_F * 4;
    __half* sBTh = (__half*)(sm + OFF_BH_F);

    const int tid  = threadIdx.x;
    const int lane = tid & 31;
    const int wid  = tid >> 5;
    const int g    = lane >> 2;
    const int q    = lane & 3;
    const int wm   = wid >> 1;      // pair id (0..7): 16 seq rows
    const int wn   = wid & 1;       // half (0..1): 64 units / 128 d
    const float bvv = bv[0];

    const uint32_t smAh_b = smem_u32(sAh);
    const uint32_t smBh_b = smem_u32(sBTh);

    // ---- one-time: B = W2^T fp16 [u][k], Wv ----
    for (int idx = tid; idx < D_ * U_; idx += 512) {
        int k = idx >> 7, u = idx & 127;
        sBTh[u * 264 + k] = __float2half_rn(W2[idx]);
    }
    for (int i = tid; i < U_; i += 512) sWv[i] = Wv[i];
    __syncthreads();

    // fixed softmax shift: M = bv + sum|Wv| (exact upper bound; tanh <= 1)
    float Mfix = bvv;
    #pragma unroll 8
    for (int i = 0; i < U_; i++) Mfix += fabsf(sWv[i]);

    // ---- ldmatrix per-thread offsets ----
    const int a_r  = (lane & 7) + (((lane >> 3) & 1) * 8);
    const int a_kb = (lane >= 16) ? 16 : 0;
    const uint32_t aoff = (uint32_t)((wm * 16 + a_r) * TROW_B + a_kb);
    const int b_r  = (lane & 7) + ((lane >= 16) ? 8 : 0);
    const int b_kb = ((lane >> 3) & 1) * 16;
    const uint32_t boff_base =
        smBh_b + (uint32_t)((wn * 64 + b_r) * TROW_B + b_kb);

    float4 va[4];
    auto ldg_phase = [&](const float* vb, int p) {
        #pragma unroll
        for (int k = 0; k < 4; k++) {
            int idx = tid + (p * 4 + k) * 512;
            int row = idx >> 6, f4 = idx & 63;
            va[k] = *reinterpret_cast<const float4*>(vb + (size_t)row * D_ + f4 * 4);
        }
    };
    auto sts_phase = [&](char* abuf, int p) {
        #pragma unroll
        for (int k = 0; k < 4; k++) {
            int idx = tid + (p * 4 + k) * 512;
            int row = idx >> 6, f4 = idx & 63;
            __half2 h0 = __floats2half2_rn(va[k].x, va[k].y);
            __half2 h1 = __floats2half2_rn(va[k].z, va[k].w);
            uint2 pk;
            pk.x = *reinterpret_cast<uint32_t*>(&h0);
            pk.y = *reinterpret_cast<uint32_t*>(&h1);
            *reinterpret_cast<uint2*>(abuf + row * TROW_B + f4 * 8) = pk;
        }
    };

    bool first = true;

    // ================= persistent unit loop =================
    for (int unit = blockIdx.x; unit < NUNIT; unit += GRID_SC) {
        const int b  = unit >> 3;
        const int ss = unit & 7;
        const int s0 = ss * 512;
        const float* vb = values + (size_t)(b * S_ + s0) * D_;

        const bool hnu = (unit + GRID_SC) < NUNIT;
        const int  bn  = (unit + GRID_SC) >> 3;
        const int  ssn = (unit + GRID_SC) & 7;

        if (first) {
            #pragma unroll
            for (int p = 0; p < 4; p++) { ldg_phase(vb, p); sts_phase(sAh, p); }
            if (tid < 128) sQ[tid] = g_qpb[b * U_ + tid];
            first = false;
            __syncthreads();
        }

        float z_local = 0.0f;
        float4 c4 = make_float4(0.f, 0.f, 0.f, 0.f);
        float qv = 0.0f;

        for (int t = 0; t < 4; t++) {
            bool hn;
            const float* vbn = vb;
            char* nbuf = sAh;
            if (t < 3) {
                hn = true;
                vbn = vb + (size_t)((t + 1) * 128) * D_;
                nbuf = sAh + ((t + 1) & 1) * ABUF_B;
            } else {
                hn = hnu;
                if (hn) {
                    vbn = values + (size_t)(bn * S_ + ssn * 512) * D_;
                    nbuf = sAh;
                    if (tid < 128) qv = g_qpb[bn * U_ + tid];
                }
            }

            float acc[8][4];
            #pragma unroll
            for (int j = 0; j < 8; j++)
                #pragma unroll
                for (int e = 0; e < 4; e++) acc[j][e] = 0.0f;

            // ---- MMA sweep over K=256 (16 k16); loads at k16 = 2,6,10,14 ----
            const uint32_t aB = smAh_b + (t & 1) * ABUF_B;
            #pragma unroll
            for (int k16 = 0; k16 < 16; k16++) {
                if ((k16 & 3) == 2 && hn) {
                    int p = k16 >> 2;
                    if (p > 0) sts_phase(nbuf, p - 1);
                    ldg_phase(vbn, p);
                }
                uint32_t a[4];
                LDSM4(a, aB + aoff + k16 * 32);
                #pragma unroll
                for (int jt = 0; jt < 4; jt++) {
                    uint32_t bf[4];
                    LDSM4(bf, boff_base + (uint32_t)(jt * 16 * TROW_B) + k16 * 32);
                    mma_f16(acc[jt * 2],     a, bf[0], bf[1]);
                    mma_f16(acc[jt * 2 + 1], a, bf[2], bf[3]);
                }
            }
            if (hn) sts_phase(nbuf, 3);

            // ======== pair-local epilogue ========
            float p0 = 0.f, p1 = 0.f;
            #pragma unroll
            for (int j = 0; j < 8; j++) {
                int ub = wn * 64 + j * 8 + q * 2;
                float w0 = sWv[ub], w1 = sWv[ub + 1];
                float q0 = sQ[ub],  q1 = sQ[ub + 1];
                p0 += tanh_approx(acc[j][0] + q0) * w0
                    + tanh_approx(acc[j][1] + q1) * w1;
                p1 += tanh_approx(acc[j][2] + q0) * w0
                    + tanh_approx(acc[j][3] + q1) * w1;
            }
            p0 += __shfl_xor_sync(0xffffffffu, p0, 1);
            p0 += __shfl_xor_sync(0xffffffffu, p0, 2);
            p1 += __shfl_xor_sync(0xffffffffu, p1, 1);
            p1 += __shfl_xor_sync(0xffffffffu, p1, 2);

            float* pb = sred + wm * 32;
            if (q == 0) {
                pb[wn * 16 + g]     = p0;
                pb[wn * 16 + g + 8] = p1;
            }
            asm volatile("bar.sync %0, 64;" :: "r"(1 + wm) : "memory");
            float e0 = __expf(pb[g]      + pb[16 + g]      + bvv - Mfix);
            float e1 = __expf(pb[g + 8]  + pb[16 + g + 8]  + bvv - Mfix);
            if (wn == 0 && q == 0) {
                size_t sb = (size_t)b * S_ + s0 + t * 128 + wm * 16;
                g_score[sb + g]     = e0;
                g_score[sb + g + 8] = e1;
                z_local += e0 + e1;
            }

            // ---- context from fp16 smem (pair rows, this warp's d-half) ----
            const char* abuf = (const char*)sAh + (t & 1) * ABUF_B
                             + (wm * 16) * TROW_B + wn * 256 + lane * 8;
            #pragma unroll
            for (int r = 0; r < 16; r++) {
                float er = __shfl_sync(0xffffffffu, (r < 8) ? e0 : e1, (r & 7) << 2);
                uint2 hv = *reinterpret_cast<const uint2*>(abuf + r * TROW_B);
                __half2 h0 = *reinterpret_cast<__half2*>(&hv.x);
                __half2 h1 = *reinterpret_cast<__half2*>(&hv.y);
                float2 f0 = __half22float2(h0);
                float2 f1 = __half22float2(h1);
                c4.x += er * f0.x; c4.y += er * f0.y;
                c4.z += er * f1.x; c4.w += er * f1.y;
            }

            __syncthreads();   // single block barrier per tile
        }

        // ---- unit end: combine context + z ----
        ((float4*)sred)[wid * 32 + lane] = c4;    // 16 warps x 128 floats
        float zs = z_local;
        #pragma unroll
        for (int off = 16; off > 0; off >>= 1)
            zs += __shfl_xor_sync(0xffffffffu, zs, off);
        if (lane == 0 && wn == 0) zbuf[wm] = zs;
        __syncthreads();
        if (tid < 256) {
            float v = 0.0f;
            int wnd = tid >> 7, l4 = tid & 127;
            #pragma unroll
            for (int m8 = 0; m8 < 8; m8++)
                v += sred[(m8 * 2 + wnd) * 128 + l4];
            g_ctxp[(size_t)ss * B_ * D_ + b * D_ + tid] = v;
        }
        if (tid == 0) {
            float z = 0.0f;
            #pragma unroll
            for (int i = 0; i < 8; i++) z += zbuf[i];
            g_zp[ss * B_ + b] = z;
        }
        if (hnu && tid < 128) sQ[tid] = qv;
        __syncthreads();
    }
}

// ---------------------------------------------------------------------------
// K3 (fused): weights = e * invZ; block (blk&3)==0 also reduces context.
//   Grid = 512 blocks x 256 thr; block covers 1024 weights (float4 x 1).
// ---------------------------------------------------------------------------
__global__ __launch_bounds__(256)
void epilogue_kernel(float* __restrict__ out_w, float* __restrict__ ctx) {
    int blk = blockIdx.x;
    int b   = blk >> 2;            // 4 blocks per batch
    int tid = threadIdx.x;

    float Z = 0.0f;
    #pragma unroll
    for (int i = 0; i < NSPLIT; i++) Z += g_zp[i * B_ + b];
    float invZ = 1.0f / Z;

    // weights: 1024 consecutive (256 thr x float4)
    size_t base = (size_t)blk * 1024 + tid * 4;
    float4 e4 = *reinterpret_cast<const float4*>(g_score + base);
    e4.x *= invZ; e4.y *= invZ; e4.z *= invZ; e4.w *= invZ;
    *reinterpret_cast<float4*>(out_w + base) = e4;

    // context reduce (one block per batch)
    if ((blk & 3) == 0) {
        float a = 0.0f;
        #pragma unroll
        for (int i = 0; i < NSPLIT; i++)
            a += g_ctxp[(size_t)i * B_ * D_ + b * D_ + tid];
        ctx[b * D_ + tid] = a * invZ;
    }
}

// ---------------------------------------------------------------------------
extern "C" void kernel_launch(void* const* d_in, const int* in_sizes, int n_in,
                              void* d_out, int out_size) {
    const float* query  = (const float*)d_in[0];
    const float* values = (const float*)d_in[1];
    const float* W1     = (const float*)d_in[2];
    const float* b1     = (const float*)d_in[3];
    const float* W2     = (const float*)d_in[4];
    const float* b2     = (const float*)d_in[5];
    const float* Wv     = (const float*)d_in[6];
    const float* bv     = (const float*)d_in[7];

    float* out  = (float*)d_out;
    float* ctx  = out;
    float* wout = out + B_ * D_;

    cudaFuncSetAttribute(score_mma_kernel,
                         cudaFuncAttributeMaxDynamicSharedMemorySize, SMEM_SC);

    qproj_kernel<<<B_, U_>>>(query, W1, b1, b2);
    score_mma_kernel<<<GRID_SC, 512, SMEM_SC>>>(values, W2, Wv, bv);
    epilogue_kernel<<<(B_ * S_) / 1024, 256>>>(wout, ctx);
}